// round 15
// baseline (speedup 1.0000x reference)
#include <cuda_runtime.h>
#include <cuda_bf16.h>
#include <math.h>

#define NB    4096
#define NTOT  8192
#define D     256
#define PP    100
#define KNEG  10

#define BM 128
#define BN 128
#define BK 64
#define NT 64
#define NTILES (NT*(NT+1)/2)   // 2080

// smem layout (bytes) for k_main: 3 stages (A16K+B16K each) + reduce
#define STAGE_BYTES 32768
#define BOFF_IN_STAGE 16384
#define RED_OFF  98304         // 8 floats
#define SMEM_BYTES 98368       // x2 CTAs = 196736 <= 228K

// -------------------- device globals (scratch) --------------------
__device__ __align__(16) __nv_bfloat16 g_nrm[NTOT * D];     // normalized rows, bf16
__device__ int    g_cntb[8][128];                           // hist partial slices
__device__ float  g_posb[NB / 8];                           // pos partials (per block)
__device__ float  g_pdn[PP * PP];
__device__ float  g_mu[PP];
__device__ float  g_var[PP];
__device__ __align__(16) __nv_bfloat16 g_coefT[104 * NTOT]; // TRANSPOSED: coefT[b][i]
__device__ double g_denom;

// -------------------- helpers --------------------
__device__ __forceinline__ unsigned smem_u32(const void* p) {
    return (unsigned)__cvta_generic_to_shared(p);
}
__device__ __forceinline__ void cp16(unsigned dst, const void* src) {
    asm volatile("cp.async.cg.shared.global [%0], [%1], 16;\n" :: "r"(dst), "l"(src));
}

// -------------------- launch 0: normalize + pos partials + hist slices + zero --------------------
__global__ void k_normalize(const float* __restrict__ x, const float* __restrict__ xa,
                            const int* __restrict__ hq) {
    int wid = threadIdx.x >> 5, lane = threadIdx.x & 31;
    int i = blockIdx.x * 8 + wid;               // 512 blocks x 8 warps
    const float4* px  = (const float4*)(x  + i * D) + lane * 2;
    const float4* pxa = (const float4*)(xa + i * D) + lane * 2;
    float4 a0 = px[0],  a1 = px[1];
    float4 b0 = pxa[0], b1 = pxa[1];
    float s1 = a0.x*a0.x + a0.y*a0.y + a0.z*a0.z + a0.w*a0.w
             + a1.x*a1.x + a1.y*a1.y + a1.z*a1.z + a1.w*a1.w;
    float s2 = b0.x*b0.x + b0.y*b0.y + b0.z*b0.z + b0.w*b0.w
             + b1.x*b1.x + b1.y*b1.y + b1.z*b1.z + b1.w*b1.w;
    float s3 = a0.x*b0.x + a0.y*b0.y + a0.z*b0.z + a0.w*b0.w
             + a1.x*b1.x + a1.y*b1.y + a1.z*b1.z + a1.w*b1.w;
    #pragma unroll
    for (int o = 16; o > 0; o >>= 1) {
        s1 += __shfl_down_sync(0xffffffffu, s1, o);
        s2 += __shfl_down_sync(0xffffffffu, s2, o);
        s3 += __shfl_down_sync(0xffffffffu, s3, o);
    }
    float n1 = fmaxf(sqrtf(s1), 1e-12f);
    float n2 = fmaxf(sqrtf(s2), 1e-12f);
    float inv1 = __shfl_sync(0xffffffffu, 1.0f / n1, 0);
    float inv2 = __shfl_sync(0xffffffffu, 1.0f / n2, 0);

    __nv_bfloat162 o1[4], o2[4];
    float va[8] = {a0.x,a0.y,a0.z,a0.w,a1.x,a1.y,a1.z,a1.w};
    float vb[8] = {b0.x,b0.y,b0.z,b0.w,b1.x,b1.y,b1.z,b1.w};
    #pragma unroll
    for (int q = 0; q < 4; q++) {
        o1[q] = __floats2bfloat162_rn(va[2*q] * inv1, va[2*q+1] * inv1);
        o2[q] = __floats2bfloat162_rn(vb[2*q] * inv2, vb[2*q+1] * inv2);
    }
    *(uint4*)(g_nrm + i * D + lane * 8)          = *(uint4*)o1;
    *(uint4*)(g_nrm + (NB + i) * D + lane * 8)   = *(uint4*)o2;

    __shared__ float pw[8];
    __shared__ int hc[PP];
    if (lane == 0) pw[wid] = s3 / (n1 * n2);

    bool histB = (blockIdx.x < 8);
    if (histB && threadIdx.x < PP) hc[threadIdx.x] = 0;
    __syncthreads();
    if (threadIdx.x == 0) {
        float t = 0.f;
        #pragma unroll
        for (int q = 0; q < 8; q++) t += pw[q];
        g_posb[blockIdx.x] = t;
        if (blockIdx.x == 0) g_denom = 0.0;
    }
    if (histB) {
        int base = blockIdx.x * 1024;
        #pragma unroll
        for (int j = 0; j < 4; j++) atomicAdd(&hc[hq[base + threadIdx.x + j * 256]], 1);
        __syncthreads();
        if (threadIdx.x < PP) g_cntb[blockIdx.x][threadIdx.x] = hc[threadIdx.x];
    }
}

// -------------------- launch 1: fused proto norms + dots + row stats (512 thr) --------------------
__global__ void k_prestats(const float* __restrict__ w) {
    int a = blockIdx.x;                      // 100 blocks
    int t = threadIdx.x, wd = t >> 5, ln = t & 31;   // 512 threads, 16 warps
    __shared__ float wa[D];
    __shared__ float dotS[PP], nbS[PP], pd[PP];
    __shared__ int   cnt[PP];
    __shared__ float red[2][16], redf[16];
    __shared__ float sh_bcast[3];

    if (t < D) wa[t] = w[a * D + t];
    if (t < PP) {
        int c = 0;
        #pragma unroll
        for (int s = 0; s < 8; s++) c += g_cntb[s][t];
        cnt[t] = c;
    }
    __syncthreads();

    for (int b = wd; b < PP; b += 16) {
        float dot = 0.f, nb = 0.f;
        #pragma unroll
        for (int q = 0; q < 8; q++) {
            float vb = w[b * D + ln + q * 32];
            dot += wa[ln + q * 32] * vb;
            nb  += vb * vb;
        }
        #pragma unroll
        for (int o = 16; o > 0; o >>= 1) {
            dot += __shfl_down_sync(0xffffffffu, dot, o);
            nb  += __shfl_down_sync(0xffffffffu, nb, o);
        }
        if (ln == 0) { dotS[b] = dot; nbS[b] = nb; }
    }
    __syncthreads();

    float inv_na = 1.0f / fmaxf(sqrtf(nbS[a]), 1e-12f);
    if (t < PP)
        pd[t] = 1.0f - dotS[t] * inv_na / fmaxf(sqrtf(nbS[t]), 1e-12f);
    __syncthreads();

    float vmin = 0.f, vmax = 0.f;
    if (t < PP) {
        bool inS = (t == a) ? (cnt[a] >= 2) : (cnt[t] >= 1);
        if (inS) { vmin = fminf(0.f, pd[t]); vmax = fmaxf(0.f, pd[t]); }
    }
    #pragma unroll
    for (int o = 16; o > 0; o >>= 1) {
        vmin = fminf(vmin, __shfl_down_sync(0xffffffffu, vmin, o));
        vmax = fmaxf(vmax, __shfl_down_sync(0xffffffffu, vmax, o));
    }
    if (ln == 0) { red[0][wd] = vmin; red[1][wd] = vmax; }
    __syncthreads();
    if (t == 0) {
        float mn = red[0][0], mx = red[1][0];
        #pragma unroll
        for (int q = 1; q < 16; q++) { mn = fminf(mn, red[0][q]); mx = fmaxf(mx, red[1][q]); }
        sh_bcast[0] = mn; sh_bcast[1] = mx;
    }
    __syncthreads();
    float rmin = sh_bcast[0];
    float inv  = 1.0f / (sh_bcast[1] - rmin);

    float pdn_t = 0.f;
    if (t < PP) {
        pdn_t = (pd[t] - rmin) * inv;
        g_pdn[a * PP + t] = pdn_t;
    }
    float pdn0  = (0.f - rmin) * inv;
    float pdnaa = (pd[a] - rmin) * inv;

    float s = (t < PP) ? (float)cnt[t] * pdn_t : 0.f;
    #pragma unroll
    for (int o = 16; o > 0; o >>= 1) s += __shfl_down_sync(0xffffffffu, s, o);
    if (ln == 0) redf[wd] = s;
    __syncthreads();
    if (t == 0) {
        float tot = 0.f;
        #pragma unroll
        for (int q = 0; q < 16; q++) tot += redf[q];
        sh_bcast[2] = (tot - pdnaa + pdn0) / (float)NTOT;
    }
    __syncthreads();
    float mu = sh_bcast[2];

    float xx = pdn_t - mu;
    float v2 = (t < PP) ? (float)cnt[t] * xx * xx : 0.f;
    #pragma unroll
    for (int o = 16; o > 0; o >>= 1) v2 += __shfl_down_sync(0xffffffffu, v2, o);
    if (ln == 0) redf[wd] = v2;
    __syncthreads();
    if (t == 0) {
        float tot = 0.f;
        #pragma unroll
        for (int q = 0; q < 16; q++) tot += redf[q];
        float x0 = pdn0 - mu, xa2 = pdnaa - mu;
        tot = tot - xa2 * xa2 + x0 * x0;
        g_mu[a]  = mu;
        g_var[a] = tot / (float)(NTOT - 1);
    }
}

// -------------------- launch 2: coef table (TRANSPOSED write) --------------------
__global__ void k_coefR(const int* __restrict__ hq, const int* __restrict__ nq) {
    int wid = threadIdx.x >> 5, lane = threadIdx.x & 31;
    int i = blockIdx.x * 8 + wid;              // 1024 blocks x 8 warps
    int v = (lane < KNEG) ? nq[i * KNEG + lane] : -1;
    int sa = __shfl_sync(0xffffffffu, (lane == 0) ? hq[i] : 0, 0);
    #pragma unroll
    for (int g = 0; g < 4; g++) {
        int col = lane + g * 32;
        bool m = false;
        #pragma unroll
        for (int k = 0; k < KNEG; k++)
            m |= (__shfl_sync(0xffffffffu, v, k) == col);
        float val = 0.f;
        if (col < PP && m) {
            float x = g_pdn[sa * PP + col] - g_mu[col];
            val = expf(x * x / (2.0f * g_var[col]));
        }
        if (col < 104) g_coefT[col * NTOT + i] = __float2bfloat16(val);
    }
}

// -------------------- launch 3: fused GEMM + epilogue (128x128, 2 CTA/SM, 3-stage) --------------------
extern __shared__ char smem_raw[];

__global__ void __launch_bounds__(256, 2) k_main(const int* __restrict__ hq) {
    // closed-form upper-triangular decode
    int id = blockIdx.x;
    int bi;
    {
        float disc = (float)((2 * NT + 1) * (2 * NT + 1) - 8 * id);
        bi = (int)(((float)(2 * NT + 1) - sqrtf(disc)) * 0.5f);
        if (bi < 0) bi = 0;
        if (bi > NT - 1) bi = NT - 1;
        while (bi > 0 && id < bi * NT - (bi * (bi - 1)) / 2) bi--;
        while (id >= (bi + 1) * NT - ((bi + 1) * bi) / 2) bi++;
    }
    int bj = bi + (id - (bi * NT - (bi * (bi - 1)) / 2));
    const bool diag = (bi == bj);
    const int rowBase = bi * BM;
    const int colBase = bj * BN;

    char* sm = smem_raw;
    int tid = threadIdx.x;
    unsigned base = smem_u32(sm);

    auto prefetch = [&](int chunk) {
        unsigned s0 = base + (unsigned)(chunk % 3) * STAGE_BYTES;
        int k0 = chunk * BK;
        #pragma unroll
        for (int it = 0; it < 4; ++it) {
            int cid = it * 256 + tid;
            int r = cid >> 3, cc = cid & 7;
            unsigned swz = (unsigned)((r * 8 + (cc ^ (r & 7))) << 4);
            cp16(s0 + swz,                 g_nrm + (rowBase + r) * D + k0 + cc * 8);
            cp16(s0 + BOFF_IN_STAGE + swz, g_nrm + (colBase + r) * D + k0 + cc * 8);
        }
        asm volatile("cp.async.commit_group;\n");
    };

    prefetch(0);
    prefetch(1);

    int lane = tid & 31;
    int wid  = tid >> 5;
    int wm = wid >> 2, wn = wid & 3;   // 2x4 warp grid; warp tile 64x32

    float acc[4][4][4];
    #pragma unroll
    for (int a0 = 0; a0 < 4; a0++)
        #pragma unroll
        for (int b0 = 0; b0 < 4; b0++)
            #pragma unroll
            for (int c0 = 0; c0 < 4; c0++) acc[a0][b0][c0] = 0.f;

    // loop-invariant ldmatrix row terms
    int ln8 = lane & 7, sub = lane >> 3;
    int rowA0 = wm * 64 + ln8 + ((sub & 1) << 3);            // + mi*16
    int ccA_h = (sub >> 1) & 1;
    int rowBx = wn * 32 + ((lane >> 4) << 3) + ln8;          // + pair*16 (x4 B)
    int ccB_h = (lane >> 3) & 1;

    #pragma unroll 1
    for (int kt = 0; kt < 4; ++kt) {
        if (kt < 3) asm volatile("cp.async.wait_group 1;\n");
        else        asm volatile("cp.async.wait_group 0;\n");
        __syncthreads();                 // chunk kt visible; stage (kt+2)%3 free (see dist-3 reuse)
        if (kt < 2) prefetch(kt + 2);
        unsigned aS = base + (unsigned)(kt % 3) * STAGE_BYTES;
        unsigned bS = aS + BOFF_IN_STAGE;
        #pragma unroll
        for (int ks = 0; ks < 4; ++ks) {
            int kk2 = ks * 2;
            unsigned af[4][4];
            unsigned bf[4][2];
            #pragma unroll
            for (int mi = 0; mi < 4; ++mi) {
                int row = rowA0 + mi * 16;
                int cc  = kk2 + ccA_h;
                unsigned addr = aS + (unsigned)((row * 8 + (cc ^ (row & 7))) << 4);
                asm volatile("ldmatrix.sync.aligned.m8n8.x4.shared.b16 {%0,%1,%2,%3}, [%4];\n"
                             : "=r"(af[mi][0]), "=r"(af[mi][1]), "=r"(af[mi][2]), "=r"(af[mi][3])
                             : "r"(addr));
            }
            #pragma unroll
            for (int pair = 0; pair < 2; ++pair) {
                int row = rowBx + pair * 16;
                int cc  = kk2 + ccB_h;
                unsigned addr = bS + (unsigned)((row * 8 + (cc ^ (row & 7))) << 4);
                asm volatile("ldmatrix.sync.aligned.m8n8.x4.shared.b16 {%0,%1,%2,%3}, [%4];\n"
                             : "=r"(bf[pair*2][0]), "=r"(bf[pair*2][1]),
                               "=r"(bf[pair*2+1][0]), "=r"(bf[pair*2+1][1])
                             : "r"(addr));
            }
            #pragma unroll
            for (int mi = 0; mi < 4; ++mi)
                #pragma unroll
                for (int ni = 0; ni < 4; ++ni)
                    asm volatile(
                        "mma.sync.aligned.m16n8k16.row.col.f32.bf16.bf16.f32 "
                        "{%0,%1,%2,%3},{%4,%5,%6,%7},{%8,%9},{%0,%1,%2,%3};\n"
                        : "+f"(acc[mi][ni][0]), "+f"(acc[mi][ni][1]),
                          "+f"(acc[mi][ni][2]), "+f"(acc[mi][ni][3])
                        : "r"(af[mi][0]), "r"(af[mi][1]), "r"(af[mi][2]), "r"(af[mi][3]),
                          "r"(bf[ni][0]), "r"(bf[ni][1]));
        }
    }

    // ---------------- epilogue: exp * (coefT[hq_j][i] + coefT[hq_i][j]) ----------------
    int g2 = lane >> 2, t4 = lane & 3;
    int hqiR[8], hqjR[8];
    #pragma unroll
    for (int mi = 0; mi < 4; ++mi) {
        hqiR[mi * 2]     = hq[rowBase + wm * 64 + mi * 16 + g2];
        hqiR[mi * 2 + 1] = hq[rowBase + wm * 64 + mi * 16 + g2 + 8];
    }
    #pragma unroll
    for (int ni = 0; ni < 4; ++ni) {
        hqjR[ni * 2]     = hq[colBase + wn * 32 + ni * 8 + 2 * t4];
        hqjR[ni * 2 + 1] = hq[colBase + wn * 32 + ni * 8 + 2 * t4 + 1];
    }
    const __nv_bfloat16* __restrict__ cT = g_coefT;
    float accs = 0.f;
    if (!diag) {
        #pragma unroll
        for (int mi = 0; mi < 4; ++mi) {
            #pragma unroll
            for (int ni = 0; ni < 4; ++ni) {
                #pragma unroll
                for (int cc = 0; cc < 4; ++cc) {
                    int ih = cc >> 1, jh = cc & 1;
                    int iL = wm * 64 + mi * 16 + g2 + ih * 8;
                    int jL = wn * 32 + ni * 8 + 2 * t4 + jh;
                    float s = acc[mi][ni][cc];
                    float wgt = __bfloat162float(cT[hqjR[ni * 2 + jh] * NTOT + rowBase + iL])
                              + __bfloat162float(cT[hqiR[mi * 2 + ih] * NTOT + colBase + jL]);
                    accs = fmaf(__expf(s * 5.0f), wgt, accs);
                }
            }
        }
    } else {
        #pragma unroll
        for (int mi = 0; mi < 4; ++mi) {
            #pragma unroll
            for (int ni = 0; ni < 4; ++ni) {
                #pragma unroll
                for (int cc = 0; cc < 4; ++cc) {
                    int ih = cc >> 1, jh = cc & 1;
                    int iL = wm * 64 + mi * 16 + g2 + ih * 8;
                    int jL = wn * 32 + ni * 8 + 2 * t4 + jh;
                    float s = acc[mi][ni][cc];
                    float wgt = __bfloat162float(cT[hqjR[ni * 2 + jh] * NTOT + rowBase + iL])
                              + __bfloat162float(cT[hqiR[mi * 2 + ih] * NTOT + colBase + jL]);
                    if (jL > iL && wgt != 0.f)
                        accs = fmaf(__expf(s * 5.0f), wgt, accs);
                }
            }
        }
    }
    #pragma unroll
    for (int o = 16; o > 0; o >>= 1) accs += __shfl_down_sync(0xffffffffu, accs, o);
    float* sred = (float*)(sm + RED_OFF);
    if (lane == 0) sred[wid] = accs;
    __syncthreads();
    if (tid == 0) {
        float tot = 0.f;
        #pragma unroll
        for (int q = 0; q < 8; q++) tot += sred[q];
        atomicAdd(&g_denom, (double)tot);
    }
}

// -------------------- launch 4: final reduce --------------------
__global__ void k_final(float* out) {
    int t = threadIdx.x;                       // 256 threads
    double p = (double)g_posb[t] + (double)g_posb[t + 256];
    #pragma unroll
    for (int o = 16; o > 0; o >>= 1) p += __shfl_down_sync(0xffffffffu, p, o);
    __shared__ double red[8];
    if ((t & 31) == 0) red[t >> 5] = p;
    __syncthreads();
    if (t == 0) {
        double pos = 0.0;
        #pragma unroll
        for (int q = 0; q < 8; q++) pos += red[q];
        double loss = log(g_denom) - pos / ((double)NB * 0.2);
        out[0] = (float)loss;
    }
}

// -------------------- launcher --------------------
extern "C" void kernel_launch(void* const* d_in, const int* in_sizes, int n_in,
                              void* d_out, int out_size) {
    const float* x  = (const float*)d_in[0];
    const float* xa = (const float*)d_in[1];
    const float* pw = (const float*)d_in[2];
    const int*   hq = (const int*)d_in[3];
    const int*   nq = (const int*)d_in[4];
    float* out = (float*)d_out;

    cudaFuncSetAttribute(k_main, cudaFuncAttributeMaxDynamicSharedMemorySize, SMEM_BYTES);

    k_normalize<<<NB / 8, 256>>>(x, xa, hq);       // launch 0
    k_prestats<<<PP, 512>>>(pw);                   // launch 1
    k_coefR<<<NTOT / 8, 256>>>(hq, nq);            // launch 2
    k_main<<<NTILES, 256, SMEM_BYTES>>>(hq);       // launch 3  <- ncu capture target
    k_final<<<1, 256>>>(out);                      // launch 4
}

// round 16
// speedup vs baseline: 1.2323x; 1.2323x over previous
#include <cuda_runtime.h>
#include <cuda_bf16.h>
#include <math.h>

#define NB    4096
#define NTOT  8192
#define D     256
#define PP    100
#define KNEG  10

#define BM 128
#define BN 128
#define BK 64
#define NT 64
#define NTILES (NT*(NT+1)/2)   // 2080

// smem layout (bytes) for k_main: 2 stages (A16K+B16K) + cA coef + hq + reduce
#define STAGE_BYTES 32768
#define BOFF_IN_STAGE 16384
#define CA_OFF   65536         // 128 x 104 bf16 = 26624
#define HQA_OFF  92160         // 512
#define HQB_OFF  92672         // 512
#define RED_OFF  93184         // 8 floats
#define FLAG_OFF 93216         // 1 int
#define DRED_OFF 93248         // 8 doubles
#define SMEM_BYTES 93376       // x2 CTAs = 186752 <= 228K

// -------------------- device globals (scratch) --------------------
__device__ __align__(16) __nv_bfloat16 g_nrm[NTOT * D];     // normalized rows, bf16
__device__ int    g_cntb[8][128];                           // hist partial slices
__device__ float  g_posb[NB / 8];                           // pos partials (per block)
__device__ float  g_pdn[PP * PP];
__device__ float  g_mu[PP];
__device__ float  g_var[PP];
__device__ __align__(16) __nv_bfloat16 g_coefb[NTOT * 104]; // member*R, bf16, stride 104
__device__ double g_denom;
__device__ unsigned g_done;

// -------------------- helpers --------------------
__device__ __forceinline__ unsigned smem_u32(const void* p) {
    return (unsigned)__cvta_generic_to_shared(p);
}
__device__ __forceinline__ void cp16(unsigned dst, const void* src) {
    asm volatile("cp.async.cg.shared.global [%0], [%1], 16;\n" :: "r"(dst), "l"(src));
}

// -------------------- launch 0: normalize + pos partials + hist slices + zero --------------------
__global__ void k_normalize(const float* __restrict__ x, const float* __restrict__ xa,
                            const int* __restrict__ hq) {
    int wid = threadIdx.x >> 5, lane = threadIdx.x & 31;
    int i = blockIdx.x * 8 + wid;               // 512 blocks x 8 warps
    const float4* px  = (const float4*)(x  + i * D) + lane * 2;
    const float4* pxa = (const float4*)(xa + i * D) + lane * 2;
    float4 a0 = px[0],  a1 = px[1];
    float4 b0 = pxa[0], b1 = pxa[1];
    float s1 = a0.x*a0.x + a0.y*a0.y + a0.z*a0.z + a0.w*a0.w
             + a1.x*a1.x + a1.y*a1.y + a1.z*a1.z + a1.w*a1.w;
    float s2 = b0.x*b0.x + b0.y*b0.y + b0.z*b0.z + b0.w*b0.w
             + b1.x*b1.x + b1.y*b1.y + b1.z*b1.z + b1.w*b1.w;
    float s3 = a0.x*b0.x + a0.y*b0.y + a0.z*b0.z + a0.w*b0.w
             + a1.x*b1.x + a1.y*b1.y + a1.z*b1.z + a1.w*b1.w;
    #pragma unroll
    for (int o = 16; o > 0; o >>= 1) {
        s1 += __shfl_down_sync(0xffffffffu, s1, o);
        s2 += __shfl_down_sync(0xffffffffu, s2, o);
        s3 += __shfl_down_sync(0xffffffffu, s3, o);
    }
    float n1 = fmaxf(sqrtf(s1), 1e-12f);
    float n2 = fmaxf(sqrtf(s2), 1e-12f);
    float inv1 = __shfl_sync(0xffffffffu, 1.0f / n1, 0);
    float inv2 = __shfl_sync(0xffffffffu, 1.0f / n2, 0);

    __nv_bfloat162 o1[4], o2[4];
    float va[8] = {a0.x,a0.y,a0.z,a0.w,a1.x,a1.y,a1.z,a1.w};
    float vb[8] = {b0.x,b0.y,b0.z,b0.w,b1.x,b1.y,b1.z,b1.w};
    #pragma unroll
    for (int q = 0; q < 4; q++) {
        o1[q] = __floats2bfloat162_rn(va[2*q] * inv1, va[2*q+1] * inv1);
        o2[q] = __floats2bfloat162_rn(vb[2*q] * inv2, vb[2*q+1] * inv2);
    }
    *(uint4*)(g_nrm + i * D + lane * 8)          = *(uint4*)o1;
    *(uint4*)(g_nrm + (NB + i) * D + lane * 8)   = *(uint4*)o2;

    __shared__ float pw[8];
    __shared__ int hc[PP];
    if (lane == 0) pw[wid] = s3 / (n1 * n2);

    bool histB = (blockIdx.x < 8);
    if (histB && threadIdx.x < PP) hc[threadIdx.x] = 0;
    __syncthreads();
    if (threadIdx.x == 0) {
        float t = 0.f;
        #pragma unroll
        for (int q = 0; q < 8; q++) t += pw[q];
        g_posb[blockIdx.x] = t;
        if (blockIdx.x == 0) { g_denom = 0.0; g_done = 0u; }
    }
    if (histB) {
        int base = blockIdx.x * 1024;
        #pragma unroll
        for (int j = 0; j < 4; j++) atomicAdd(&hc[hq[base + threadIdx.x + j * 256]], 1);
        __syncthreads();
        if (threadIdx.x < PP) g_cntb[blockIdx.x][threadIdx.x] = hc[threadIdx.x];
    }
}

// -------------------- launch 1: fused proto norms + dots + row stats (512 thr) --------------------
__global__ void k_prestats(const float* __restrict__ w) {
    int a = blockIdx.x;                      // 100 blocks
    int t = threadIdx.x, wd = t >> 5, ln = t & 31;   // 512 threads, 16 warps
    __shared__ float wa[D];
    __shared__ float dotS[PP], nbS[PP], pd[PP];
    __shared__ int   cnt[PP];
    __shared__ float red[2][16], redf[16];
    __shared__ float sh_bcast[3];

    if (t < D) wa[t] = w[a * D + t];
    if (t < PP) {
        int c = 0;
        #pragma unroll
        for (int s = 0; s < 8; s++) c += g_cntb[s][t];
        cnt[t] = c;
    }
    __syncthreads();

    for (int b = wd; b < PP; b += 16) {
        float dot = 0.f, nb = 0.f;
        #pragma unroll
        for (int q = 0; q < 8; q++) {
            float vb = w[b * D + ln + q * 32];
            dot += wa[ln + q * 32] * vb;
            nb  += vb * vb;
        }
        #pragma unroll
        for (int o = 16; o > 0; o >>= 1) {
            dot += __shfl_down_sync(0xffffffffu, dot, o);
            nb  += __shfl_down_sync(0xffffffffu, nb, o);
        }
        if (ln == 0) { dotS[b] = dot; nbS[b] = nb; }
    }
    __syncthreads();

    float inv_na = 1.0f / fmaxf(sqrtf(nbS[a]), 1e-12f);
    if (t < PP)
        pd[t] = 1.0f - dotS[t] * inv_na / fmaxf(sqrtf(nbS[t]), 1e-12f);
    __syncthreads();

    float vmin = 0.f, vmax = 0.f;
    if (t < PP) {
        bool inS = (t == a) ? (cnt[a] >= 2) : (cnt[t] >= 1);
        if (inS) { vmin = fminf(0.f, pd[t]); vmax = fmaxf(0.f, pd[t]); }
    }
    #pragma unroll
    for (int o = 16; o > 0; o >>= 1) {
        vmin = fminf(vmin, __shfl_down_sync(0xffffffffu, vmin, o));
        vmax = fmaxf(vmax, __shfl_down_sync(0xffffffffu, vmax, o));
    }
    if (ln == 0) { red[0][wd] = vmin; red[1][wd] = vmax; }
    __syncthreads();
    if (t == 0) {
        float mn = red[0][0], mx = red[1][0];
        #pragma unroll
        for (int q = 1; q < 16; q++) { mn = fminf(mn, red[0][q]); mx = fmaxf(mx, red[1][q]); }
        sh_bcast[0] = mn; sh_bcast[1] = mx;
    }
    __syncthreads();
    float rmin = sh_bcast[0];
    float inv  = 1.0f / (sh_bcast[1] - rmin);

    float pdn_t = 0.f;
    if (t < PP) {
        pdn_t = (pd[t] - rmin) * inv;
        g_pdn[a * PP + t] = pdn_t;
    }
    float pdn0  = (0.f - rmin) * inv;
    float pdnaa = (pd[a] - rmin) * inv;

    float s = (t < PP) ? (float)cnt[t] * pdn_t : 0.f;
    #pragma unroll
    for (int o = 16; o > 0; o >>= 1) s += __shfl_down_sync(0xffffffffu, s, o);
    if (ln == 0) redf[wd] = s;
    __syncthreads();
    if (t == 0) {
        float tot = 0.f;
        #pragma unroll
        for (int q = 0; q < 16; q++) tot += redf[q];
        sh_bcast[2] = (tot - pdnaa + pdn0) / (float)NTOT;
    }
    __syncthreads();
    float mu = sh_bcast[2];

    float xx = pdn_t - mu;
    float v2 = (t < PP) ? (float)cnt[t] * xx * xx : 0.f;
    #pragma unroll
    for (int o = 16; o > 0; o >>= 1) v2 += __shfl_down_sync(0xffffffffu, v2, o);
    if (ln == 0) redf[wd] = v2;
    __syncthreads();
    if (t == 0) {
        float tot = 0.f;
        #pragma unroll
        for (int q = 0; q < 16; q++) tot += redf[q];
        float x0 = pdn0 - mu, xa2 = pdnaa - mu;
        tot = tot - xa2 * xa2 + x0 * x0;
        g_mu[a]  = mu;
        g_var[a] = tot / (float)(NTOT - 1);
    }
}

// -------------------- launch 2: coef table (row-major) --------------------
__global__ void k_coefR(const int* __restrict__ hq, const int* __restrict__ nq) {
    int wid = threadIdx.x >> 5, lane = threadIdx.x & 31;
    int i = blockIdx.x * 8 + wid;              // 1024 blocks x 8 warps
    int v = (lane < KNEG) ? nq[i * KNEG + lane] : -1;
    int sa = __shfl_sync(0xffffffffu, (lane == 0) ? hq[i] : 0, 0);
    #pragma unroll
    for (int g = 0; g < 4; g++) {
        int col = lane + g * 32;
        bool m = false;
        #pragma unroll
        for (int k = 0; k < KNEG; k++)
            m |= (__shfl_sync(0xffffffffu, v, k) == col);
        float val = 0.f;
        if (col < PP && m) {
            float x = g_pdn[sa * PP + col] - g_mu[col];
            val = expf(x * x / (2.0f * g_var[col]));
        }
        if (col < 104) g_coefb[i * 104 + col] = __float2bfloat16(val);
    }
}

// -------------------- launch 3: fused GEMM + epilogue + final (128x128, 2 CTA/SM) --------------------
extern __shared__ char smem_raw[];

__global__ void __launch_bounds__(256, 2) k_main(const int* __restrict__ hq, float* out) {
    // closed-form upper-triangular decode
    int id = blockIdx.x;
    int bi;
    {
        float disc = (float)((2 * NT + 1) * (2 * NT + 1) - 8 * id);
        bi = (int)(((float)(2 * NT + 1) - sqrtf(disc)) * 0.5f);
        if (bi < 0) bi = 0;
        if (bi > NT - 1) bi = NT - 1;
        while (bi > 0 && id < bi * NT - (bi * (bi - 1)) / 2) bi--;
        while (id >= (bi + 1) * NT - ((bi + 1) * bi) / 2) bi++;
    }
    int bj = bi + (id - (bi * NT - (bi * (bi - 1)) / 2));
    const bool diag = (bi == bj);
    const int rowBase = bi * BM;
    const int colBase = bj * BN;

    char* sm = smem_raw;
    const __nv_bfloat16* cA = (const __nv_bfloat16*)(sm + CA_OFF);
    const int* hqA = (const int*)(sm + HQA_OFF);
    const int* hqB = (const int*)(sm + HQB_OFF);

    int tid = threadIdx.x;
    unsigned base = smem_u32(sm);

    auto prefetch = [&](int chunk) {
        unsigned s0 = base + (unsigned)(chunk & 1) * STAGE_BYTES;
        int k0 = chunk * BK;
        #pragma unroll
        for (int it = 0; it < 4; ++it) {
            int cid = it * 256 + tid;
            int r = cid >> 3, cc = cid & 7;
            unsigned swz = (unsigned)((r * 8 + (cc ^ (r & 7))) << 4);
            cp16(s0 + swz,                 g_nrm + (rowBase + r) * D + k0 + cc * 8);
            cp16(s0 + BOFF_IN_STAGE + swz, g_nrm + (colBase + r) * D + k0 + cc * 8);
        }
    };

    // group0: cA coef + hq + chunk0  (the measured-best R13 arrangement)
    {
        unsigned c0 = base + CA_OFF;
        for (int idx = tid; idx < 128 * 13; idx += 256) {
            int r = idx / 13, seg = idx % 13;
            cp16(c0 + (unsigned)(r * 208 + seg * 16),
                 g_coefb + (rowBase + r) * 104 + seg * 8);
        }
        if (tid < 64) {
            int side = tid >= 32;
            int w = side ? tid - 32 : tid;
            unsigned dst = side ? (base + HQB_OFF + (unsigned)w * 16)
                                : (base + HQA_OFF + (unsigned)w * 16);
            cp16(dst, hq + (side ? colBase : rowBase) + w * 4);
        }
    }
    prefetch(0);
    asm volatile("cp.async.commit_group;\n");

    int lane = tid & 31;
    int wid  = tid >> 5;
    int wm = wid >> 2, wn = wid & 3;   // 2x4 warp grid; warp tile 64x32

    float acc[4][4][4];
    #pragma unroll
    for (int a0 = 0; a0 < 4; a0++)
        #pragma unroll
        for (int b0 = 0; b0 < 4; b0++)
            #pragma unroll
            for (int c0 = 0; c0 < 4; c0++) acc[a0][b0][c0] = 0.f;

    // loop-invariant ldmatrix row terms
    int ln8 = lane & 7, sub = lane >> 3;
    int rowA0 = wm * 64 + ln8 + ((sub & 1) << 3);            // + mi*16
    int ccA_h = (sub >> 1) & 1;
    int rowBx = wn * 32 + ((lane >> 4) << 3) + ln8;          // + pair*16 (x4 B)
    int ccB_h = (lane >> 3) & 1;

    #pragma unroll 1
    for (int kt = 0; kt < 4; ++kt) {
        asm volatile("cp.async.wait_group 0;\n");
        __syncthreads();                 // chunk kt visible CTA-wide; other stage free
        if (kt < 3) {
            prefetch(kt + 1);            // overlaps with compute below (other stage)
            asm volatile("cp.async.commit_group;\n");
        }
        unsigned aS = base + (unsigned)(kt & 1) * STAGE_BYTES;
        unsigned bS = aS + BOFF_IN_STAGE;
        #pragma unroll
        for (int ks = 0; ks < 4; ++ks) {
            int kk2 = ks * 2;
            unsigned af[4][4];
            unsigned bf[4][2];
            #pragma unroll
            for (int mi = 0; mi < 4; ++mi) {
                int row = rowA0 + mi * 16;
                int cc  = kk2 + ccA_h;
                unsigned addr = aS + (unsigned)((row * 8 + (cc ^ (row & 7))) << 4);
                asm volatile("ldmatrix.sync.aligned.m8n8.x4.shared.b16 {%0,%1,%2,%3}, [%4];\n"
                             : "=r"(af[mi][0]), "=r"(af[mi][1]), "=r"(af[mi][2]), "=r"(af[mi][3])
                             : "r"(addr));
            }
            #pragma unroll
            for (int pair = 0; pair < 2; ++pair) {
                int row = rowBx + pair * 16;
                int cc  = kk2 + ccB_h;
                unsigned addr = bS + (unsigned)((row * 8 + (cc ^ (row & 7))) << 4);
                asm volatile("ldmatrix.sync.aligned.m8n8.x4.shared.b16 {%0,%1,%2,%3}, [%4];\n"
                             : "=r"(bf[pair*2][0]), "=r"(bf[pair*2][1]),
                               "=r"(bf[pair*2+1][0]), "=r"(bf[pair*2+1][1])
                             : "r"(addr));
            }
            #pragma unroll
            for (int mi = 0; mi < 4; ++mi)
                #pragma unroll
                for (int ni = 0; ni < 4; ++ni)
                    asm volatile(
                        "mma.sync.aligned.m16n8k16.row.col.f32.bf16.bf16.f32 "
                        "{%0,%1,%2,%3},{%4,%5,%6,%7},{%8,%9},{%0,%1,%2,%3};\n"
                        : "+f"(acc[mi][ni][0]), "+f"(acc[mi][ni][1]),
                          "+f"(acc[mi][ni][2]), "+f"(acc[mi][ni][3])
                        : "r"(af[mi][0]), "r"(af[mi][1]), "r"(af[mi][2]), "r"(af[mi][3]),
                          "r"(bf[ni][0]), "r"(bf[ni][1]));
        }
    }

    // ---------------- epilogue: exp * (cA_smem + cB_global) ----------------
    int g2 = lane >> 2, t4 = lane & 3;
    int hqiR[8], hqjR[8];
    #pragma unroll
    for (int mi = 0; mi < 4; ++mi) {
        hqiR[mi * 2]     = hqA[wm * 64 + mi * 16 + g2];
        hqiR[mi * 2 + 1] = hqA[wm * 64 + mi * 16 + g2 + 8];
    }
    #pragma unroll
    for (int ni = 0; ni < 4; ++ni) {
        hqjR[ni * 2]     = hqB[wn * 32 + ni * 8 + 2 * t4];
        hqjR[ni * 2 + 1] = hqB[wn * 32 + ni * 8 + 2 * t4 + 1];
    }
    const __nv_bfloat16* __restrict__ gcB = g_coefb + (size_t)colBase * 104;
    float accs = 0.f;
    if (!diag) {
        #pragma unroll
        for (int mi = 0; mi < 4; ++mi) {
            #pragma unroll
            for (int ni = 0; ni < 4; ++ni) {
                #pragma unroll
                for (int cc = 0; cc < 4; ++cc) {
                    int ih = cc >> 1, jh = cc & 1;
                    int iL = wm * 64 + mi * 16 + g2 + ih * 8;
                    int jL = wn * 32 + ni * 8 + 2 * t4 + jh;
                    float s = acc[mi][ni][cc];
                    float wgt = __bfloat162float(cA[iL * 104 + hqjR[ni * 2 + jh]])
                              + __bfloat162float(gcB[jL * 104 + hqiR[mi * 2 + ih]]);
                    accs = fmaf(__expf(s * 5.0f), wgt, accs);
                }
            }
        }
    } else {
        #pragma unroll
        for (int mi = 0; mi < 4; ++mi) {
            #pragma unroll
            for (int ni = 0; ni < 4; ++ni) {
                #pragma unroll
                for (int cc = 0; cc < 4; ++cc) {
                    int ih = cc >> 1, jh = cc & 1;
                    int iL = wm * 64 + mi * 16 + g2 + ih * 8;
                    int jL = wn * 32 + ni * 8 + 2 * t4 + jh;
                    float s = acc[mi][ni][cc];
                    float wgt = __bfloat162float(cA[iL * 104 + hqjR[ni * 2 + jh]])
                              + __bfloat162float(gcB[jL * 104 + hqiR[mi * 2 + ih]]);
                    if (jL > iL && wgt != 0.f)
                        accs = fmaf(__expf(s * 5.0f), wgt, accs);
                }
            }
        }
    }
    #pragma unroll
    for (int o = 16; o > 0; o >>= 1) accs += __shfl_down_sync(0xffffffffu, accs, o);
    float* sred = (float*)(sm + RED_OFF);
    int* flag = (int*)(sm + FLAG_OFF);
    if (lane == 0) sred[wid] = accs;
    __syncthreads();
    if (tid == 0) {
        float tot = 0.f;
        #pragma unroll
        for (int q = 0; q < 8; q++) tot += sred[q];
        atomicAdd(&g_denom, (double)tot);
        __threadfence();
        unsigned old = atomicAdd(&g_done, 1u);
        *flag = (old == (unsigned)(NTILES - 1)) ? 1 : 0;
    }
    __syncthreads();

    // last CTA computes the final loss (replaces k_final launch)
    if (*flag) {
        double p = (double)g_posb[tid] + (double)g_posb[tid + 256];
        #pragma unroll
        for (int o = 16; o > 0; o >>= 1) p += __shfl_down_sync(0xffffffffu, p, o);
        double* dred = (double*)(sm + DRED_OFF);
        if (lane == 0) dred[wid] = p;
        __syncthreads();
        if (tid == 0) {
            double pos = 0.0;
            #pragma unroll
            for (int q = 0; q < 8; q++) pos += dred[q];
            double denom = atomicAdd(&g_denom, 0.0);   // coherent read via L2
            out[0] = (float)(log(denom) - pos / ((double)NB * 0.2));
        }
    }
}

// -------------------- launcher --------------------
extern "C" void kernel_launch(void* const* d_in, const int* in_sizes, int n_in,
                              void* d_out, int out_size) {
    const float* x  = (const float*)d_in[0];
    const float* xa = (const float*)d_in[1];
    const float* pw = (const float*)d_in[2];
    const int*   hq = (const int*)d_in[3];
    const int*   nq = (const int*)d_in[4];
    float* out = (float*)d_out;

    cudaFuncSetAttribute(k_main, cudaFuncAttributeMaxDynamicSharedMemorySize, SMEM_BYTES);

    k_normalize<<<NB / 8, 256>>>(x, xa, hq);       // launch 0
    k_prestats<<<PP, 512>>>(pw);                   // launch 1
    k_coefR<<<NTOT / 8, 256>>>(hq, nq);            // launch 2
    k_main<<<NTILES, 256, SMEM_BYTES>>>(hq, out);  // launch 3  <- ncu capture target
}

// round 17
// speedup vs baseline: 1.2951x; 1.0510x over previous
#include <cuda_runtime.h>
#include <cuda_bf16.h>
#include <math.h>

#define NB    4096
#define NTOT  8192
#define D     256
#define PP    100
#define KNEG  10

#define BM 128
#define BN 128
#define BK 64
#define NT 64
#define NTILES (NT*(NT+1)/2)   // 2080

// smem layout (bytes) for k_main: 2 stages (A16K+B16K) + cA coef + hq + reduce
#define STAGE_BYTES 32768
#define BOFF_IN_STAGE 16384
#define CA_OFF   65536         // 128 x 104 bf16 = 26624
#define HQA_OFF  92160         // 512
#define HQB_OFF  92672         // 512
#define RED_OFF  93184         // 8 floats
#define SMEM_BYTES 93248       // x2 CTAs = 186496 <= 228K

// -------------------- device globals (scratch) --------------------
__device__ __align__(16) __nv_bfloat16 g_nrm[NTOT * D];     // normalized rows, bf16
__device__ int    g_cntb[8][128];                           // hist partial slices
__device__ float  g_posb[NB / 8];                           // pos partials (per block)
__device__ float  g_pdn[PP * PP];
__device__ float  g_mu[PP];
__device__ float  g_var[PP];
__device__ __align__(16) __nv_bfloat16 g_coefb[NTOT * 104]; // member*R, bf16, stride 104
__device__ double g_denom;

// -------------------- helpers --------------------
__device__ __forceinline__ unsigned smem_u32(const void* p) {
    return (unsigned)__cvta_generic_to_shared(p);
}
__device__ __forceinline__ void cp16(unsigned dst, const void* src) {
    asm volatile("cp.async.cg.shared.global [%0], [%1], 16;\n" :: "r"(dst), "l"(src));
}

// -------------------- launch 0: normalize + pos partials + hist slices + zero --------------------
__global__ void k_normalize(const float* __restrict__ x, const float* __restrict__ xa,
                            const int* __restrict__ hq) {
    int wid = threadIdx.x >> 5, lane = threadIdx.x & 31;
    int i = blockIdx.x * 8 + wid;               // 512 blocks x 8 warps
    const float4* px  = (const float4*)(x  + i * D) + lane * 2;
    const float4* pxa = (const float4*)(xa + i * D) + lane * 2;
    float4 a0 = px[0],  a1 = px[1];
    float4 b0 = pxa[0], b1 = pxa[1];
    float s1 = a0.x*a0.x + a0.y*a0.y + a0.z*a0.z + a0.w*a0.w
             + a1.x*a1.x + a1.y*a1.y + a1.z*a1.z + a1.w*a1.w;
    float s2 = b0.x*b0.x + b0.y*b0.y + b0.z*b0.z + b0.w*b0.w
             + b1.x*b1.x + b1.y*b1.y + b1.z*b1.z + b1.w*b1.w;
    float s3 = a0.x*b0.x + a0.y*b0.y + a0.z*b0.z + a0.w*b0.w
             + a1.x*b1.x + a1.y*b1.y + a1.z*b1.z + a1.w*b1.w;
    #pragma unroll
    for (int o = 16; o > 0; o >>= 1) {
        s1 += __shfl_down_sync(0xffffffffu, s1, o);
        s2 += __shfl_down_sync(0xffffffffu, s2, o);
        s3 += __shfl_down_sync(0xffffffffu, s3, o);
    }
    float n1 = fmaxf(sqrtf(s1), 1e-12f);
    float n2 = fmaxf(sqrtf(s2), 1e-12f);
    float inv1 = __shfl_sync(0xffffffffu, 1.0f / n1, 0);
    float inv2 = __shfl_sync(0xffffffffu, 1.0f / n2, 0);

    __nv_bfloat162 o1[4], o2[4];
    float va[8] = {a0.x,a0.y,a0.z,a0.w,a1.x,a1.y,a1.z,a1.w};
    float vb[8] = {b0.x,b0.y,b0.z,b0.w,b1.x,b1.y,b1.z,b1.w};
    #pragma unroll
    for (int q = 0; q < 4; q++) {
        o1[q] = __floats2bfloat162_rn(va[2*q] * inv1, va[2*q+1] * inv1);
        o2[q] = __floats2bfloat162_rn(vb[2*q] * inv2, vb[2*q+1] * inv2);
    }
    *(uint4*)(g_nrm + i * D + lane * 8)          = *(uint4*)o1;
    *(uint4*)(g_nrm + (NB + i) * D + lane * 8)   = *(uint4*)o2;

    __shared__ float pw[8];
    __shared__ int hc[PP];
    if (lane == 0) pw[wid] = s3 / (n1 * n2);

    bool histB = (blockIdx.x < 8);
    if (histB && threadIdx.x < PP) hc[threadIdx.x] = 0;
    __syncthreads();
    if (threadIdx.x == 0) {
        float t = 0.f;
        #pragma unroll
        for (int q = 0; q < 8; q++) t += pw[q];
        g_posb[blockIdx.x] = t;
        if (blockIdx.x == 0) g_denom = 0.0;
    }
    if (histB) {
        int base = blockIdx.x * 1024;
        #pragma unroll
        for (int j = 0; j < 4; j++) atomicAdd(&hc[hq[base + threadIdx.x + j * 256]], 1);
        __syncthreads();
        if (threadIdx.x < PP) g_cntb[blockIdx.x][threadIdx.x] = hc[threadIdx.x];
    }
}

// -------------------- launch 1: fused proto norms + dots + row stats (512 thr) --------------------
__global__ void k_prestats(const float* __restrict__ w) {
    int a = blockIdx.x;                      // 100 blocks
    int t = threadIdx.x, wd = t >> 5, ln = t & 31;   // 512 threads, 16 warps
    __shared__ float wa[D];
    __shared__ float dotS[PP], nbS[PP], pd[PP];
    __shared__ int   cnt[PP];
    __shared__ float red[2][16], redf[16];
    __shared__ float sh_bcast[3];

    if (t < D) wa[t] = w[a * D + t];
    if (t < PP) {
        int c = 0;
        #pragma unroll
        for (int s = 0; s < 8; s++) c += g_cntb[s][t];
        cnt[t] = c;
    }
    __syncthreads();

    for (int b = wd; b < PP; b += 16) {
        float dot = 0.f, nb = 0.f;
        #pragma unroll
        for (int q = 0; q < 8; q++) {
            float vb = w[b * D + ln + q * 32];
            dot += wa[ln + q * 32] * vb;
            nb  += vb * vb;
        }
        #pragma unroll
        for (int o = 16; o > 0; o >>= 1) {
            dot += __shfl_down_sync(0xffffffffu, dot, o);
            nb  += __shfl_down_sync(0xffffffffu, nb, o);
        }
        if (ln == 0) { dotS[b] = dot; nbS[b] = nb; }
    }
    __syncthreads();

    float inv_na = 1.0f / fmaxf(sqrtf(nbS[a]), 1e-12f);
    if (t < PP)
        pd[t] = 1.0f - dotS[t] * inv_na / fmaxf(sqrtf(nbS[t]), 1e-12f);
    __syncthreads();

    float vmin = 0.f, vmax = 0.f;
    if (t < PP) {
        bool inS = (t == a) ? (cnt[a] >= 2) : (cnt[t] >= 1);
        if (inS) { vmin = fminf(0.f, pd[t]); vmax = fmaxf(0.f, pd[t]); }
    }
    #pragma unroll
    for (int o = 16; o > 0; o >>= 1) {
        vmin = fminf(vmin, __shfl_down_sync(0xffffffffu, vmin, o));
        vmax = fmaxf(vmax, __shfl_down_sync(0xffffffffu, vmax, o));
    }
    if (ln == 0) { red[0][wd] = vmin; red[1][wd] = vmax; }
    __syncthreads();
    if (t == 0) {
        float mn = red[0][0], mx = red[1][0];
        #pragma unroll
        for (int q = 1; q < 16; q++) { mn = fminf(mn, red[0][q]); mx = fmaxf(mx, red[1][q]); }
        sh_bcast[0] = mn; sh_bcast[1] = mx;
    }
    __syncthreads();
    float rmin = sh_bcast[0];
    float inv  = 1.0f / (sh_bcast[1] - rmin);

    float pdn_t = 0.f;
    if (t < PP) {
        pdn_t = (pd[t] - rmin) * inv;
        g_pdn[a * PP + t] = pdn_t;
    }
    float pdn0  = (0.f - rmin) * inv;
    float pdnaa = (pd[a] - rmin) * inv;

    float s = (t < PP) ? (float)cnt[t] * pdn_t : 0.f;
    #pragma unroll
    for (int o = 16; o > 0; o >>= 1) s += __shfl_down_sync(0xffffffffu, s, o);
    if (ln == 0) redf[wd] = s;
    __syncthreads();
    if (t == 0) {
        float tot = 0.f;
        #pragma unroll
        for (int q = 0; q < 16; q++) tot += redf[q];
        sh_bcast[2] = (tot - pdnaa + pdn0) / (float)NTOT;
    }
    __syncthreads();
    float mu = sh_bcast[2];

    float xx = pdn_t - mu;
    float v2 = (t < PP) ? (float)cnt[t] * xx * xx : 0.f;
    #pragma unroll
    for (int o = 16; o > 0; o >>= 1) v2 += __shfl_down_sync(0xffffffffu, v2, o);
    if (ln == 0) redf[wd] = v2;
    __syncthreads();
    if (t == 0) {
        float tot = 0.f;
        #pragma unroll
        for (int q = 0; q < 16; q++) tot += redf[q];
        float x0 = pdn0 - mu, xa2 = pdnaa - mu;
        tot = tot - xa2 * xa2 + x0 * x0;
        g_mu[a]  = mu;
        g_var[a] = tot / (float)(NTOT - 1);
    }
}

// -------------------- launch 2: coef table (row-major) --------------------
__global__ void k_coefR(const int* __restrict__ hq, const int* __restrict__ nq) {
    int wid = threadIdx.x >> 5, lane = threadIdx.x & 31;
    int i = blockIdx.x * 8 + wid;              // 1024 blocks x 8 warps
    int v = (lane < KNEG) ? nq[i * KNEG + lane] : -1;
    int sa = __shfl_sync(0xffffffffu, (lane == 0) ? hq[i] : 0, 0);
    #pragma unroll
    for (int g = 0; g < 4; g++) {
        int col = lane + g * 32;
        bool m = false;
        #pragma unroll
        for (int k = 0; k < KNEG; k++)
            m |= (__shfl_sync(0xffffffffu, v, k) == col);
        float val = 0.f;
        if (col < PP && m) {
            float x = g_pdn[sa * PP + col] - g_mu[col];
            val = expf(x * x / (2.0f * g_var[col]));
        }
        if (col < 104) g_coefb[i * 104 + col] = __float2bfloat16(val);
    }
}

// -------------------- launch 3: fused GEMM + epilogue (128x128, 2 CTA/SM) --------------------
extern __shared__ char smem_raw[];

__global__ void __launch_bounds__(256, 2) k_main(const int* __restrict__ hq) {
    // closed-form upper-triangular decode
    int id = blockIdx.x;
    int bi;
    {
        float disc = (float)((2 * NT + 1) * (2 * NT + 1) - 8 * id);
        bi = (int)(((float)(2 * NT + 1) - sqrtf(disc)) * 0.5f);
        if (bi < 0) bi = 0;
        if (bi > NT - 1) bi = NT - 1;
        while (bi > 0 && id < bi * NT - (bi * (bi - 1)) / 2) bi--;
        while (id >= (bi + 1) * NT - ((bi + 1) * bi) / 2) bi++;
    }
    int bj = bi + (id - (bi * NT - (bi * (bi - 1)) / 2));
    const bool diag = (bi == bj);
    const int rowBase = bi * BM;
    const int colBase = bj * BN;

    char* sm = smem_raw;
    const __nv_bfloat16* cA = (const __nv_bfloat16*)(sm + CA_OFF);
    const int* hqA = (const int*)(sm + HQA_OFF);
    const int* hqB = (const int*)(sm + HQB_OFF);

    int tid = threadIdx.x;
    unsigned base = smem_u32(sm);

    auto prefetch = [&](int chunk) {
        unsigned s0 = base + (unsigned)(chunk & 1) * STAGE_BYTES;
        int k0 = chunk * BK;
        #pragma unroll
        for (int it = 0; it < 4; ++it) {
            int cid = it * 256 + tid;
            int r = cid >> 3, cc = cid & 7;
            unsigned swz = (unsigned)((r * 8 + (cc ^ (r & 7))) << 4);
            cp16(s0 + swz,                 g_nrm + (rowBase + r) * D + k0 + cc * 8);
            cp16(s0 + BOFF_IN_STAGE + swz, g_nrm + (colBase + r) * D + k0 + cc * 8);
        }
    };

    // group0: cA coef + hq + chunk0  (measured-best arrangement, R13)
    {
        unsigned c0 = base + CA_OFF;
        for (int idx = tid; idx < 128 * 13; idx += 256) {
            int r = idx / 13, seg = idx % 13;
            cp16(c0 + (unsigned)(r * 208 + seg * 16),
                 g_coefb + (rowBase + r) * 104 + seg * 8);
        }
        if (tid < 64) {
            int side = tid >= 32;
            int w = side ? tid - 32 : tid;
            unsigned dst = side ? (base + HQB_OFF + (unsigned)w * 16)
                                : (base + HQA_OFF + (unsigned)w * 16);
            cp16(dst, hq + (side ? colBase : rowBase) + w * 4);
        }
    }
    prefetch(0);
    asm volatile("cp.async.commit_group;\n");

    int lane = tid & 31;
    int wid  = tid >> 5;
    int wm = wid >> 2, wn = wid & 3;   // 2x4 warp grid; warp tile 64x32

    float acc[4][4][4];
    #pragma unroll
    for (int a0 = 0; a0 < 4; a0++)
        #pragma unroll
        for (int b0 = 0; b0 < 4; b0++)
            #pragma unroll
            for (int c0 = 0; c0 < 4; c0++) acc[a0][b0][c0] = 0.f;

    // loop-invariant ldmatrix row terms
    int ln8 = lane & 7, sub = lane >> 3;
    int rowA0 = wm * 64 + ln8 + ((sub & 1) << 3);            // + mi*16
    int ccA_h = (sub >> 1) & 1;
    int rowBx = wn * 32 + ((lane >> 4) << 3) + ln8;          // + pair*16 (x4 B)
    int ccB_h = (lane >> 3) & 1;

    #pragma unroll 1
    for (int kt = 0; kt < 4; ++kt) {
        asm volatile("cp.async.wait_group 0;\n");
        __syncthreads();                 // chunk kt visible CTA-wide; other stage free
        if (kt < 3) {
            prefetch(kt + 1);            // overlaps with compute below (other stage)
            asm volatile("cp.async.commit_group;\n");
        }
        unsigned aS = base + (unsigned)(kt & 1) * STAGE_BYTES;
        unsigned bS = aS + BOFF_IN_STAGE;
        #pragma unroll
        for (int ks = 0; ks < 4; ++ks) {
            int kk2 = ks * 2;
            unsigned af[4][4];
            unsigned bf[4][2];
            #pragma unroll
            for (int mi = 0; mi < 4; ++mi) {
                int row = rowA0 + mi * 16;
                int cc  = kk2 + ccA_h;
                unsigned addr = aS + (unsigned)((row * 8 + (cc ^ (row & 7))) << 4);
                asm volatile("ldmatrix.sync.aligned.m8n8.x4.shared.b16 {%0,%1,%2,%3}, [%4];\n"
                             : "=r"(af[mi][0]), "=r"(af[mi][1]), "=r"(af[mi][2]), "=r"(af[mi][3])
                             : "r"(addr));
            }
            #pragma unroll
            for (int pair = 0; pair < 2; ++pair) {
                int row = rowBx + pair * 16;
                int cc  = kk2 + ccB_h;
                unsigned addr = bS + (unsigned)((row * 8 + (cc ^ (row & 7))) << 4);
                asm volatile("ldmatrix.sync.aligned.m8n8.x4.shared.b16 {%0,%1,%2,%3}, [%4];\n"
                             : "=r"(bf[pair*2][0]), "=r"(bf[pair*2][1]),
                               "=r"(bf[pair*2+1][0]), "=r"(bf[pair*2+1][1])
                             : "r"(addr));
            }
            #pragma unroll
            for (int mi = 0; mi < 4; ++mi)
                #pragma unroll
                for (int ni = 0; ni < 4; ++ni)
                    asm volatile(
                        "mma.sync.aligned.m16n8k16.row.col.f32.bf16.bf16.f32 "
                        "{%0,%1,%2,%3},{%4,%5,%6,%7},{%8,%9},{%0,%1,%2,%3};\n"
                        : "+f"(acc[mi][ni][0]), "+f"(acc[mi][ni][1]),
                          "+f"(acc[mi][ni][2]), "+f"(acc[mi][ni][3])
                        : "r"(af[mi][0]), "r"(af[mi][1]), "r"(af[mi][2]), "r"(af[mi][3]),
                          "r"(bf[ni][0]), "r"(bf[ni][1]));
        }
    }

    // ---------------- epilogue: exp * (cA_smem + cB_global) ----------------
    int g2 = lane >> 2, t4 = lane & 3;
    int hqiR[8], hqjR[8];
    #pragma unroll
    for (int mi = 0; mi < 4; ++mi) {
        hqiR[mi * 2]     = hqA[wm * 64 + mi * 16 + g2];
        hqiR[mi * 2 + 1] = hqA[wm * 64 + mi * 16 + g2 + 8];
    }
    #pragma unroll
    for (int ni = 0; ni < 4; ++ni) {
        hqjR[ni * 2]     = hqB[wn * 32 + ni * 8 + 2 * t4];
        hqjR[ni * 2 + 1] = hqB[wn * 32 + ni * 8 + 2 * t4 + 1];
    }
    const __nv_bfloat16* __restrict__ gcB = g_coefb + (size_t)colBase * 104;
    float accs = 0.f;
    if (!diag) {
        #pragma unroll
        for (int mi = 0; mi < 4; ++mi) {
            #pragma unroll
            for (int ni = 0; ni < 4; ++ni) {
                #pragma unroll
                for (int cc = 0; cc < 4; ++cc) {
                    int ih = cc >> 1, jh = cc & 1;
                    int iL = wm * 64 + mi * 16 + g2 + ih * 8;
                    int jL = wn * 32 + ni * 8 + 2 * t4 + jh;
                    float s = acc[mi][ni][cc];
                    float wgt = __bfloat162float(cA[iL * 104 + hqjR[ni * 2 + jh]])
                              + __bfloat162float(gcB[jL * 104 + hqiR[mi * 2 + ih]]);
                    accs = fmaf(__expf(s * 5.0f), wgt, accs);
                }
            }
        }
    } else {
        #pragma unroll
        for (int mi = 0; mi < 4; ++mi) {
            #pragma unroll
            for (int ni = 0; ni < 4; ++ni) {
                #pragma unroll
                for (int cc = 0; cc < 4; ++cc) {
                    int ih = cc >> 1, jh = cc & 1;
                    int iL = wm * 64 + mi * 16 + g2 + ih * 8;
                    int jL = wn * 32 + ni * 8 + 2 * t4 + jh;
                    float s = acc[mi][ni][cc];
                    float wgt = __bfloat162float(cA[iL * 104 + hqjR[ni * 2 + jh]])
                              + __bfloat162float(gcB[jL * 104 + hqiR[mi * 2 + ih]]);
                    if (jL > iL && wgt != 0.f)
                        accs = fmaf(__expf(s * 5.0f), wgt, accs);
                }
            }
        }
    }
    #pragma unroll
    for (int o = 16; o > 0; o >>= 1) accs += __shfl_down_sync(0xffffffffu, accs, o);
    float* sred = (float*)(sm + RED_OFF);
    if (lane == 0) sred[wid] = accs;
    __syncthreads();
    if (tid == 0) {
        float tot = 0.f;
        #pragma unroll
        for (int q = 0; q < 8; q++) tot += sred[q];
        atomicAdd(&g_denom, (double)tot);
    }
}

// -------------------- launch 4: final reduce --------------------
__global__ void k_final(float* out) {
    int t = threadIdx.x;                       // 256 threads
    double p = (double)g_posb[t] + (double)g_posb[t + 256];
    #pragma unroll
    for (int o = 16; o > 0; o >>= 1) p += __shfl_down_sync(0xffffffffu, p, o);
    __shared__ double red[8];
    if ((t & 31) == 0) red[t >> 5] = p;
    __syncthreads();
    if (t == 0) {
        double pos = 0.0;
        #pragma unroll
        for (int q = 0; q < 8; q++) pos += red[q];
        double loss = log(g_denom) - pos / ((double)NB * 0.2);
        out[0] = (float)loss;
    }
}

// -------------------- launcher --------------------
extern "C" void kernel_launch(void* const* d_in, const int* in_sizes, int n_in,
                              void* d_out, int out_size) {
    const float* x  = (const float*)d_in[0];
    const float* xa = (const float*)d_in[1];
    const float* pw = (const float*)d_in[2];
    const int*   hq = (const int*)d_in[3];
    const int*   nq = (const int*)d_in[4];
    float* out = (float*)d_out;

    cudaFuncSetAttribute(k_main, cudaFuncAttributeMaxDynamicSharedMemorySize, SMEM_BYTES);

    k_normalize<<<NB / 8, 256>>>(x, xa, hq);       // launch 0
    k_prestats<<<PP, 512>>>(pw);                   // launch 1
    k_coefR<<<NTOT / 8, 256>>>(hq, nq);            // launch 2
    k_main<<<NTILES, 256, SMEM_BYTES>>>(hq);       // launch 3  <- ncu capture target
    k_final<<<1, 256>>>(out);                      // launch 4
}